// round 14
// baseline (speedup 1.0000x reference)
#include <cuda_runtime.h>
#include <math.h>

#define C_    256
#define T_    8
#define H_    32
#define W_    32
#define L_    4
#define THW_  8192
#define NROWS 256
#define FEAT_OUT_ELEMS (C_*THW_*L_)   // 2097152
#define NB 256                        // 256 blocks x 256 threads, 2/SM co-resident
#define NBG 8

// ---- scratch (device globals; no allocation) ----
__device__ float    g_XT [512*256];    // X transposed (feat|pos): [k][row]
__device__ float    g_H1T[256*256];    // H1 transposed: [k][row]
__device__ float    g_H2 [256*256];    // H2 row-major
__device__ float    g_glob[4*256];
__device__ unsigned g_grp_cnt[32*64];  // level-1 arrival counters (256B apart)
__device__ unsigned g_root_cnt[64];    // level-2 counter (own line)
__device__ unsigned g_root_gen[64];    // generation flag (own line)
__device__ unsigned g_gbar[2][32*64];  // pairwise group bars

__constant__ int c_tt[4] = {1,3,4,6};
__constant__ int c_hh[4] = {4,12,19,27};

__device__ __forceinline__ int flat_idx(int n){
    int it = n >> 4, ih = (n >> 2) & 3, iw = n & 3;
    return (c_tt[it]*H_ + c_hh[ih])*W_ + c_hh[iw];
}
__device__ __forceinline__ float sigmoidf_(float x){ return 1.0f/(1.0f+expf(-x)); }
__device__ __forceinline__ float invsigf_(float x){
    return logf(fmaxf(x,1e-5f)/fmaxf(1.0f-x,1e-5f));
}
__device__ __forceinline__ void cp_async16(void* smem_dst, const void* gmem_src){
    unsigned s = (unsigned)__cvta_generic_to_shared(smem_dst);
    asm volatile("cp.async.cg.shared.global [%0], [%1], 16;\n" :: "r"(s), "l"(gmem_src));
}
__device__ __forceinline__ void cp_commit(){ asm volatile("cp.async.commit_group;\n"); }
__device__ __forceinline__ void cp_wait0(){ asm volatile("cp.async.wait_group 0;\n"); }
__device__ __forceinline__ void cp_wait1(){ asm volatile("cp.async.wait_group 1;\n"); }

typedef unsigned long long ull;
__device__ __forceinline__ ull fma2_(ull a, ull b, ull c){
    ull d; asm("fma.rn.f32x2 %0, %1, %2, %3;" : "=l"(d) : "l"(a), "l"(b), "l"(c)); return d;
}
__device__ __forceinline__ ull pack2_(float x, float y){
    ull r; asm("mov.b64 %0, {%1, %2};" : "=l"(r) : "f"(x), "f"(y)); return r;
}
__device__ __forceinline__ float2 unpack2_(ull v){
    float2 r; asm("mov.b64 {%0, %1}, %2;" : "=f"(r.x), "=f"(r.y) : "l"(v)); return r;
}

// Two-level global barrier: 32 group lines -> root counter -> generation flag.
// All counters monotonic (replay/graph safe).
__device__ __forceinline__ void global_bar(int b){
    __syncthreads();
    if (threadIdx.x == 0){
        __threadfence();
        int grp = b >> 3;                               // 32 groups of 8
        unsigned old = atomicAdd(&g_grp_cnt[grp*64], 1u);
        unsigned gen_goal = old / (unsigned)NBG + 1u;   // this barrier's generation
        if ((old % (unsigned)NBG) == (unsigned)(NBG-1)){
            unsigned o2 = atomicAdd(&g_root_cnt[0], 1u);
            if ((o2 % 32u) == 31u)
                atomicAdd(&g_root_gen[0], 1u);          // release generation
        }
        volatile unsigned* gp = &g_root_gen[0];
        while ((int)(*gp - gen_goal) < 0) __nanosleep(128);
        __threadfence();
    }
    __syncthreads();
}
__device__ __forceinline__ void group_bar(int id, int g){
    __syncthreads();
    if (threadIdx.x == 0){
        __threadfence();
        unsigned* cnt = &g_gbar[id][g*64];
        unsigned old  = atomicAdd(cnt, 1u);
        unsigned goal = old - (old % (unsigned)NBG) + (unsigned)NBG;
        volatile unsigned* p = cnt;
        while ((int)(*p - goal) < 0) __nanosleep(64);
        __threadfence();
    }
    __syncthreads();
}

// ============================================================
// GEMM phase: Out = relu(X[256,K] @ W[K,256] + bias [+G])
// X k-major. 256 blocks x 256 threads; tile 8 rows x 32 cols.
// ============================================================
#define XD_ULL 1024
#define WF_F   4096

__device__ __forceinline__ void prime_W(const float* __restrict__ Wg, float* Wf,
                                        int c0, int t){
    #pragma unroll
    for (int u = 0; u < 4; u++){
        int idx4 = t + u*256;
        int wk = idx4 >> 3, ws = idx4 & 7;
        cp_async16(Wf + wk*32 + ws*4, Wg + (size_t)wk*256 + c0 + ws*4);
    }
    cp_commit();
}

template<int NCH, bool WRITE_T>
__device__ __forceinline__ void gemm_phase(
    const float* __restrict__ XT, const float* __restrict__ Wg,
    const float* __restrict__ bias, const float* Gadd,
    float* __restrict__ Out, ull* Xd, float* Wf)
{
    int t  = threadIdx.x;
    int c0 = ((int)blockIdx.x & 7) * 32;
    int r0 = ((int)blockIdx.x >> 3) * 8;
    int rp = t & 3, qc = (t >> 2) & 7, ks = t >> 5;
    int kk = t >> 1, seg = t & 1;

    {
        float4 xv = *(const float4*)(XT + (size_t)kk*256 + r0 + seg*4);
        ull* dst = Xd + kk*8 + seg*4;
        ulonglong2 d0, d1;
        d0.x = pack2_(xv.x, xv.x); d0.y = pack2_(xv.y, xv.y);
        d1.x = pack2_(xv.z, xv.z); d1.y = pack2_(xv.w, xv.w);
        *(ulonglong2*)dst = d0;
        *(ulonglong2*)(dst+2) = d1;
    }

    ull aA0=0ULL, aA1=0ULL, aB0=0ULL, aB1=0ULL;
    float4 xn;

    #pragma unroll 1
    for (int ch = 0; ch < NCH; ch++){
        ull*   Xc = Xd + (ch & 1)*XD_ULL;
        float* Wc = Wf + (ch & 1)*WF_F;
        if (ch + 1 < NCH){
            float* Wn2 = Wf + ((ch+1)&1)*WF_F;
            #pragma unroll
            for (int u = 0; u < 4; u++){
                int idx4 = t + u*256;
                int wk = idx4 >> 3, ws = idx4 & 7;
                cp_async16(Wn2 + wk*32 + ws*4,
                           Wg + (size_t)((ch+1)*128 + wk)*256 + c0 + ws*4);
            }
            cp_commit();
            xn = *(const float4*)(XT + (size_t)((ch+1)*128 + kk)*256 + r0 + seg*4);
            cp_wait1();
        } else {
            cp_wait0();
        }
        __syncthreads();

        const ull*   xb = Xc + (ks*16)*8 + 2*rp;
        const float* wb = Wc + (ks*16)*32 + qc*4;
        #pragma unroll 4
        for (int k2 = 0; k2 < 16; k2++){
            ulonglong2 xd = *(const ulonglong2*)(xb + k2*8);
            ulonglong2 wv = *(const ulonglong2*)(wb + k2*32);
            aA0 = fma2_(wv.x, xd.x, aA0);
            aA1 = fma2_(wv.y, xd.x, aA1);
            aB0 = fma2_(wv.x, xd.y, aB0);
            aB1 = fma2_(wv.y, xd.y, aB1);
        }
        __syncthreads();

        if (ch + 1 < NCH){
            ull* dst = Xd + ((ch+1)&1)*XD_ULL + kk*8 + seg*4;
            ulonglong2 d0, d1;
            d0.x = pack2_(xn.x, xn.x); d0.y = pack2_(xn.y, xn.y);
            d1.x = pack2_(xn.z, xn.z); d1.y = pack2_(xn.w, xn.w);
            *(ulonglong2*)dst = d0;
            *(ulonglong2*)(dst+2) = d1;
        }
    }

    ull* PART = Xd;
    {
        ull* dst = PART + (size_t)t*4;
        ulonglong2 p0, p1;
        p0.x = aA0; p0.y = aA1;
        p1.x = aB0; p1.y = aB1;
        *(ulonglong2*)dst = p0;
        *(ulonglong2*)(dst+2) = p1;
    }
    __syncthreads();

    if (t < 32){
        int prp = t & 3, pqc = (t >> 2) & 7;
        float2 e01 = make_float2(0.f,0.f), e23 = e01, o01 = e01, o23 = e01;
        #pragma unroll
        for (int s = 0; s < 8; s++){
            const ull* e = PART + (size_t)(s*32 + t)*4;
            ulonglong2 u0 = *(const ulonglong2*)e;
            ulonglong2 u1 = *(const ulonglong2*)(e+2);
            float2 f;
            f = unpack2_(u0.x); e01.x += f.x; e01.y += f.y;
            f = unpack2_(u0.y); e23.x += f.x; e23.y += f.y;
            f = unpack2_(u1.x); o01.x += f.x; o01.y += f.y;
            f = unpack2_(u1.y); o23.x += f.x; o23.y += f.y;
        }
        float4 bb = *(const float4*)(bias + c0 + pqc*4);
        if (Gadd){
            bb.x += Gadd[pqc*4+0]; bb.y += Gadd[pqc*4+1];
            bb.z += Gadd[pqc*4+2]; bb.w += Gadd[pqc*4+3];
        }
        float ve0 = fmaxf(e01.x + bb.x, 0.f), ve1 = fmaxf(e01.y + bb.y, 0.f);
        float ve2 = fmaxf(e23.x + bb.z, 0.f), ve3 = fmaxf(e23.y + bb.w, 0.f);
        float vo0 = fmaxf(o01.x + bb.x, 0.f), vo1 = fmaxf(o01.y + bb.y, 0.f);
        float vo2 = fmaxf(o23.x + bb.z, 0.f), vo3 = fmaxf(o23.y + bb.w, 0.f);
        int re = r0 + 2*prp, cA = c0 + pqc*4;
        if (WRITE_T){
            *(float2*)(Out + (size_t)(cA+0)*256 + re) = make_float2(ve0, vo0);
            *(float2*)(Out + (size_t)(cA+1)*256 + re) = make_float2(ve1, vo1);
            *(float2*)(Out + (size_t)(cA+2)*256 + re) = make_float2(ve2, vo2);
            *(float2*)(Out + (size_t)(cA+3)*256 + re) = make_float2(ve3, vo3);
        } else {
            *(float4*)(Out + (size_t)re*256 + cA)     = make_float4(ve0, ve1, ve2, ve3);
            *(float4*)(Out + (size_t)(re+1)*256 + cA) = make_float4(vo0, vo1, vo2, vo3);
        }
    }
    __syncthreads();
}

// ============================================================
#define FUSED_SMEM_BYTES 49152

__global__ void __launch_bounds__(256, 2)
fused_kernel(const float* __restrict__ feats, const float* __restrict__ pos,
             const float* __restrict__ W1, const float* __restrict__ b1,
             const float* __restrict__ W2, const float* __restrict__ b2,
             const float* __restrict__ Wn, const float* __restrict__ bn,
             const float* __restrict__ Woff, const float* __restrict__ boff,
             const float* __restrict__ Ww, const float* __restrict__ bw,
             const float* __restrict__ gamma, const float* __restrict__ beta,
             float* __restrict__ out, int write_next)
{
    extern __shared__ ull smu[];
    ull*   Xd = smu;
    float* Wf = (float*)(smu + 2*XD_ULL);

    __shared__ float  Hs[256];
    __shared__ float  HWn[768], HWo[192], HWw[128];
    __shared__ float  HD[28];
    __shared__ float  SPx[4], SPy[4], SPz[4], SPw[4];
    __shared__ int    cq[40];
    __shared__ float  cw[40];
    __shared__ int    s_nq;
    __shared__ float2 sred[8];
    __shared__ float  s_mu, s_rstd;
    __shared__ float  Gpart[256], Gs[32], glS[256];

    int t = threadIdx.x;
    int b = blockIdx.x;
    int g = b >> 3;
    int c0 = (b & 7) * 32;
    int l_blk = b >> 6;

    prime_W(W1, Wf, c0, t);

    // ---- phase A1: XT gathers for channel b (feat | pos)
    {
        int l = t >> 6;
        int p = flat_idx(t & 63);
        g_XT[(size_t)b*256 + t]       = feats[((size_t)b*THW_ + p)*L_ + l];
        g_XT[(size_t)(256+b)*256 + t] = pos  [((size_t)b*THW_ + p)*L_ + l];
    }

    // ---- phase A2: channel-b mean scan (4 independent float4 chains)
    {
        const float4* f4 = reinterpret_cast<const float4*>(feats + (size_t)b*(THW_*L_));
        float4 a0 = make_float4(0,0,0,0), a1 = a0, a2 = a0, a3 = a0;
        #pragma unroll
        for (int j = 0; j < 8; j++){
            float4 v0 = f4[t + (4*j+0)*256];
            float4 v1 = f4[t + (4*j+1)*256];
            float4 v2 = f4[t + (4*j+2)*256];
            float4 v3 = f4[t + (4*j+3)*256];
            a0.x+=v0.x; a0.y+=v0.y; a0.z+=v0.z; a0.w+=v0.w;
            a1.x+=v1.x; a1.y+=v1.y; a1.z+=v1.z; a1.w+=v1.w;
            a2.x+=v2.x; a2.y+=v2.y; a2.z+=v2.z; a2.w+=v2.w;
            a3.x+=v3.x; a3.y+=v3.y; a3.z+=v3.z; a3.w+=v3.w;
        }
        float4 a = make_float4(a0.x+a1.x+a2.x+a3.x, a0.y+a1.y+a2.y+a3.y,
                               a0.z+a1.z+a2.z+a3.z, a0.w+a1.w+a2.w+a3.w);
        const unsigned full = 0xffffffffu;
        #pragma unroll
        for (int o = 16; o > 0; o >>= 1){
            a.x += __shfl_xor_sync(full, a.x, o);
            a.y += __shfl_xor_sync(full, a.y, o);
            a.z += __shfl_xor_sync(full, a.z, o);
            a.w += __shfl_xor_sync(full, a.w, o);
        }
        float4* sm4 = (float4*)smu;       // overlays Xd (free until GEMM1)
        int wid = t >> 5, lane = t & 31;
        if (lane == 0) sm4[wid] = a;
        __syncthreads();
        if (t == 0){
            float4 s = make_float4(0,0,0,0);
            #pragma unroll
            for (int w2 = 0; w2 < 8; w2++){
                float4 v = sm4[w2];
                s.x+=v.x; s.y+=v.y; s.z+=v.z; s.w+=v.w;
            }
            const float inv = 1.0f/8192.0f;
            g_glob[0*256+b] = s.x*inv;
            g_glob[1*256+b] = s.y*inv;
            g_glob[2*256+b] = s.z*inv;
            g_glob[3*256+b] = s.w*inv;
        }
    }

    global_bar(b);                      // XT + g_glob complete chip-wide

    // ---- phase B: beta fill — moved AFTER bar (off the slowest-block path;
    // STG.128s are fire-and-forget, DRAM drain overlaps GEMM1)
    {
        float4* out4 = (float4*)out;
        const unsigned tm = 0x5Au;
        const unsigned hm = (1u<<4)|(1u<<12)|(1u<<19)|(1u<<27);
        #pragma unroll
        for (int u = 0; u < 8; u++){
            int f = b*2048 + u*256 + t;
            int c = f >> 13;
            int p = f & 8191;
            int t3 = p >> 10, h3 = (p >> 5) & 31, w3 = p & 31;
            bool samp = ((tm >> t3) & 1u) && ((hm >> h3) & 1u) && ((hm >> w3) & 1u);
            if (!samp){
                float bb = __ldg(&beta[c]);
                out4[f] = make_float4(bb, bb, bb, bb);
            }
        }
    }

    // ---- phase C0: G[j] = sum_c glob[l_blk][c] * W1[512+c][c0+j]
    glS[t] = g_glob[l_blk*256 + t];
    __syncthreads();
    {
        int j = t & 31, cs = t >> 5;
        const float* wp = W1 + (size_t)(512 + cs*32)*256 + c0 + j;
        float s0 = 0.f, s1 = 0.f;
        #pragma unroll
        for (int ci = 0; ci < 32; ci += 2){
            s0 = fmaf(glS[cs*32+ci],   __ldg(wp + (size_t)ci*256),     s0);
            s1 = fmaf(glS[cs*32+ci+1], __ldg(wp + (size_t)(ci+1)*256), s1);
        }
        Gpart[cs*32 + j] = s0 + s1;
    }
    __syncthreads();
    if (t < 32){
        float s = 0.f;
        #pragma unroll
        for (int cs = 0; cs < 8; cs++) s += Gpart[cs*32 + t];
        Gs[t] = s;
    }
    __syncthreads();

    // ---- phase C: GEMM1 (K=512) -> g_H1T (+G fold)
    gemm_phase<4, true>(g_XT, W1, b1, Gs, g_H1T, Xd, Wf);

    prime_W(W2, Wf, c0, t);
    group_bar(0, g);

    // ---- phase D: GEMM2 (K=256) -> g_H2
    gemm_phase<2, false>(g_H1T, W2, b2, nullptr, g_H2, Xd, Wf);
    group_bar(1, g);

    // ---- phase E: heads (28 parallel 8-lane dots) + dedup, row rr = b
    int rr = b;
    int p  = flat_idx(rr & 63);

    Hs[t] = g_H2[(size_t)rr*256 + t];
    for (int k = t; k < 768; k += 256) HWn[k] = __ldg(&Wn[k]);
    if (t < 192) HWo[t] = __ldg(&Woff[t]);
    if (t < 128) HWw[t] = __ldg(&Ww[t]);
    __syncthreads();

    {
        int oid = t >> 3, sl = t & 7;
        float s = 0.f;
        if (oid < 3){
            #pragma unroll 8
            for (int i = 0; i < 32; i++){
                int k = sl + 8*i;
                s = fmaf(Hs[k], HWn[k*3 + oid], s);
            }
        } else if (oid >= 8 && oid < 20){
            int v = oid - 8;
            int no = v / 3, jo = v - no*3;
            #pragma unroll
            for (int i = 0; i < 8; i++){
                int dd = sl + 8*i;
                s = fmaf(Hs[no*64+dd], HWo[dd*3 + jo], s);
            }
        } else if (oid >= 20 && oid < 28){
            int v = oid - 20;
            int no = v >> 1, comp = v & 1;
            #pragma unroll
            for (int i = 0; i < 8; i++){
                int dd = sl + 8*i;
                s = fmaf(Hs[no*64+dd], HWw[dd*2 + comp], s);
            }
        }
        const unsigned full = 0xffffffffu;
        s += __shfl_xor_sync(full, s, 4);
        s += __shfl_xor_sync(full, s, 2);
        s += __shfl_xor_sync(full, s, 1);
        if (sl == 0 && oid < 28) HD[oid] = s;
    }
    __syncthreads();

    if (t == 0){
        int tq = p >> 10, hq = (p >> 5) & 31, wq = p & 31;
        float tn = (float)tq * (1.0f/7.0f);
        float hn = (float)hq * (1.0f/31.0f);
        float wn = (float)wq * (1.0f/31.0f);
        float ivt = invsigf_(tn), ivh = invsigf_(hn), ivw = invsigf_(wn);
        float bo0 = boff[0], bo1 = boff[1], bo2 = boff[2];
        float bw0 = bw[0],  bw1 = bw[1];

        #pragma unroll
        for (int no = 0; no < 4; no++){
            float o0 = HD[8+no*3+0] + bo0;
            float o1 = HD[8+no*3+1] + bo1;
            float o2 = HD[8+no*3+2] + bo2;
            float st = sigmoidf_(ivt + o0)*2.0f - 1.0f;
            float sh = sigmoidf_(ivh + o1)*2.0f - 1.0f;
            float sw = sigmoidf_(ivw + o2)*2.0f - 1.0f;
            SPx[no] = ((st + 1.0f)*32.0f - 1.0f)*0.5f;
            SPy[no] = ((sh + 1.0f)*32.0f - 1.0f)*0.5f;
            SPz[no] = ((sw + 1.0f)*8.0f  - 1.0f)*0.5f;
            float za = HD[20+no*2] + bw0, zb = HD[21+no*2] + bw1;
            SPw[no] = 1.0f/(1.0f + expf(za - zb));
        }

        if (write_next){
            float d0 = sigmoidf_(ivt + HD[0] + bn[0]) * 7.0f;
            float d1 = sigmoidf_(ivh + HD[1] + bn[1]) * 31.0f;
            float d2 = sigmoidf_(ivw + HD[2] + bn[2]) * 31.0f;
            int ni = 1024*(int)rintf(d0) + 32*(int)rintf(d1) + (int)rintf(d2);
            out[FEAT_OUT_ELEMS + rr] = (float)ni;
        }
    }
    __syncthreads();

    if (t < 32){
        const unsigned full = 0xffffffffu;
        int lane = t;
        int no = lane >> 3, jj = lane & 7;
        float ix = SPx[no], iy = SPy[no], iz = SPz[no];
        float wo = SPw[no];
        float x0f = floorf(ix), y0f = floorf(iy), z0f = floorf(iz);
        int dx = jj & 1, dy = (jj >> 1) & 1, dz = jj >> 2;
        int xi = (int)x0f + dx, yi = (int)y0f + dy, zi = (int)z0f + dz;
        float fx = ix - x0f, fy = iy - y0f, fz = iz - z0f;
        float w = (dx ? fx : 1.0f-fx) * (dy ? fy : 1.0f-fy) * (dz ? fz : 1.0f-fz) * wo;
        bool valid = (xi >= 0) & (xi < W_) & (yi >= 0) & (yi < H_) & (zi >= 0) & (zi < T_);
        if (!valid) w = 0.0f;
        int q = (min(max(zi,0),T_-1)*H_ + min(max(yi,0),H_-1))*W_ + min(max(xi,0),W_-1);

        unsigned mask = __match_any_sync(full, q);
        float wsum = 0.0f;
        #pragma unroll
        for (int s2 = 0; s2 < 32; s2++){
            float wv = __shfl_sync(full, w, s2);
            int   qv = __shfl_sync(full, q, s2);
            if (qv == q) wsum += wv;
        }
        int leader = __ffs(mask) - 1;
        bool is_leader = (lane == leader);
        unsigned bal = __ballot_sync(full, is_leader);
        int pos = __popc(bal & ((1u << lane) - 1u));
        if (is_leader){ cq[pos] = q; cw[pos] = wsum; }
        __syncwarp();
        if (lane == 0){
            int nq = __popc(bal);
            bool found = false;
            for (int j2 = 0; j2 < nq; j2++){
                if (cq[j2] == p){ cw[j2] += 1.0f; found = true; break; }
            }
            if (!found){ cq[nq] = p; cw[nq] = 1.0f; nq++; }
            s_nq = nq;
        }
    }
    __syncthreads();

    // ---- phase F: sample + LN, row rr
    {
        int l  = rr >> 6;
        int c  = t;
        int nq = s_nq;
        const float* fb = feats + (size_t)c*(THW_*L_) + l;
        float acc = 0.0f;
        #pragma unroll 4
        for (int j2 = 0; j2 < nq; j2++)
            acc = fmaf(cw[j2], __ldg(fb + (size_t)cq[j2]*L_), acc);
        float v = acc;

        const unsigned full = 0xffffffffu;
        float sx = v, sy = v*v;
        #pragma unroll
        for (int o = 16; o > 0; o >>= 1){
            sx += __shfl_xor_sync(full, sx, o);
            sy += __shfl_xor_sync(full, sy, o);
        }
        int lane = t & 31, wrp = t >> 5;
        if (lane == 0) sred[wrp] = make_float2(sx, sy);
        __syncthreads();
        if (t == 0){
            float mx = 0.f, my = 0.f;
            #pragma unroll
            for (int k = 0; k < 8; k++){ mx += sred[k].x; my += sred[k].y; }
            float mu  = mx * (1.0f/256.0f);
            float var = my * (1.0f/256.0f) - mu*mu;
            s_mu = mu;
            s_rstd = rsqrtf(var + 1e-5f);
        }
        __syncthreads();

        float o = (v - s_mu) * s_rstd * __ldg(&gamma[c]) + __ldg(&beta[c]);
        out[((size_t)c*THW_ + p)*L_ + l] = o;
    }
}

// ============================================================
extern "C" void kernel_launch(void* const* d_in, const int* in_sizes, int n_in,
                              void* d_out, int out_size)
{
    const float* feats = (const float*)d_in[0];
    const float* pos   = (const float*)d_in[1];
    const float* W1    = (const float*)d_in[2];
    const float* b1    = (const float*)d_in[3];
    const float* W2    = (const float*)d_in[4];
    const float* b2    = (const float*)d_in[5];
    const float* Wn    = (const float*)d_in[6];
    const float* bn    = (const float*)d_in[7];
    // d_in[8]=Wl, d_in[9]=bl dead (softmax row-sum == 1; LN scale-invariant)
    const float* Woff  = (const float*)d_in[10];
    const float* boff  = (const float*)d_in[11];
    const float* Ww    = (const float*)d_in[12];
    const float* bw    = (const float*)d_in[13];
    const float* gamma = (const float*)d_in[14];
    const float* beta  = (const float*)d_in[15];
    float* out = (float*)d_out;

    int write_next = (out_size >= FEAT_OUT_ELEMS + NROWS) ? 1 : 0;

    static int smem_set = 0;
    if (!smem_set){
        cudaFuncSetAttribute(fused_kernel, cudaFuncAttributeMaxDynamicSharedMemorySize,
                             FUSED_SMEM_BYTES);
        smem_set = 1;
    }

    fused_kernel<<<NB, 256, FUSED_SMEM_BYTES>>>(feats, pos, W1, b1, W2, b2, Wn, bn,
                                                Woff, boff, Ww, bw, gamma, beta,
                                                out, write_next);
}

// round 15
// speedup vs baseline: 1.0713x; 1.0713x over previous
#include <cuda_runtime.h>
#include <math.h>

#define C_    256
#define T_    8
#define H_    32
#define W_    32
#define L_    4
#define THW_  8192
#define NROWS 256
#define FEAT_OUT_ELEMS (C_*THW_*L_)   // 2097152
#define NB 256
#define NBG 8

// ---- scratch (device globals; no allocation) ----
__device__ float    g_XT [512*256];    // X transposed (feat|pos): [k][row]
__device__ float    g_H1T[256*256];    // H1 transposed: [k][row]
__device__ float    g_H2 [256*256];    // H2 row-major
__device__ float    g_glob[4*256];
__device__ unsigned g_gbar[2][32*64];  // group bars (monotonic, replay-safe)

__constant__ int c_tt[4] = {1,3,4,6};
__constant__ int c_hh[4] = {4,12,19,27};

__device__ __forceinline__ int flat_idx(int n){
    int it = n >> 4, ih = (n >> 2) & 3, iw = n & 3;
    return (c_tt[it]*H_ + c_hh[ih])*W_ + c_hh[iw];
}
__device__ __forceinline__ float sigmoidf_(float x){ return 1.0f/(1.0f+expf(-x)); }
__device__ __forceinline__ float invsigf_(float x){
    return logf(fmaxf(x,1e-5f)/fmaxf(1.0f-x,1e-5f));
}
__device__ __forceinline__ void cp_async16(void* smem_dst, const void* gmem_src){
    unsigned s = (unsigned)__cvta_generic_to_shared(smem_dst);
    asm volatile("cp.async.cg.shared.global [%0], [%1], 16;\n" :: "r"(s), "l"(gmem_src));
}
__device__ __forceinline__ void cp_commit(){ asm volatile("cp.async.commit_group;\n"); }
__device__ __forceinline__ void cp_wait0(){ asm volatile("cp.async.wait_group 0;\n"); }
__device__ __forceinline__ void cp_wait1(){ asm volatile("cp.async.wait_group 1;\n"); }

typedef unsigned long long ull;
__device__ __forceinline__ ull fma2_(ull a, ull b, ull c){
    ull d; asm("fma.rn.f32x2 %0, %1, %2, %3;" : "=l"(d) : "l"(a), "l"(b), "l"(c)); return d;
}
__device__ __forceinline__ ull pack2_(float x, float y){
    ull r; asm("mov.b64 %0, {%1, %2};" : "=l"(r) : "f"(x), "f"(y)); return r;
}
__device__ __forceinline__ float2 unpack2_(ull v){
    float2 r; asm("mov.b64 {%0, %1}, %2;" : "=f"(r.x), "=f"(r.y) : "l"(v)); return r;
}

__device__ __forceinline__ void group_bar(int id, int g){
    __syncthreads();
    if (threadIdx.x == 0){
        __threadfence();
        unsigned* cnt = &g_gbar[id][g*64];
        unsigned old  = atomicAdd(cnt, 1u);
        unsigned goal = old - (old % (unsigned)NBG) + (unsigned)NBG;
        volatile unsigned* p = cnt;
        while ((int)(*p - goal) < 0) __nanosleep(64);
        __threadfence();
    }
    __syncthreads();
}

// ============================================================
// Kernel 1: channel-mean scan + XT gathers. One block per channel.
// ============================================================
__global__ void __launch_bounds__(256)
scan_kernel(const float* __restrict__ feats, const float* __restrict__ pos)
{
    int b = blockIdx.x;                 // channel
    int t = threadIdx.x;

    // XT gathers (feat | pos)
    {
        int l = t >> 6;
        int p = flat_idx(t & 63);
        g_XT[(size_t)b*256 + t]       = feats[((size_t)b*THW_ + p)*L_ + l];
        g_XT[(size_t)(256+b)*256 + t] = pos  [((size_t)b*THW_ + p)*L_ + l];
    }

    // channel mean scan, 4 independent float4 chains
    const float4* f4 = reinterpret_cast<const float4*>(feats + (size_t)b*(THW_*L_));
    float4 a0 = make_float4(0,0,0,0), a1 = a0, a2 = a0, a3 = a0;
    #pragma unroll
    for (int j = 0; j < 8; j++){
        float4 v0 = f4[t + (4*j+0)*256];
        float4 v1 = f4[t + (4*j+1)*256];
        float4 v2 = f4[t + (4*j+2)*256];
        float4 v3 = f4[t + (4*j+3)*256];
        a0.x+=v0.x; a0.y+=v0.y; a0.z+=v0.z; a0.w+=v0.w;
        a1.x+=v1.x; a1.y+=v1.y; a1.z+=v1.z; a1.w+=v1.w;
        a2.x+=v2.x; a2.y+=v2.y; a2.z+=v2.z; a2.w+=v2.w;
        a3.x+=v3.x; a3.y+=v3.y; a3.z+=v3.z; a3.w+=v3.w;
    }
    float4 a = make_float4(a0.x+a1.x+a2.x+a3.x, a0.y+a1.y+a2.y+a3.y,
                           a0.z+a1.z+a2.z+a3.z, a0.w+a1.w+a2.w+a3.w);
    const unsigned full = 0xffffffffu;
    #pragma unroll
    for (int o = 16; o > 0; o >>= 1){
        a.x += __shfl_xor_sync(full, a.x, o);
        a.y += __shfl_xor_sync(full, a.y, o);
        a.z += __shfl_xor_sync(full, a.z, o);
        a.w += __shfl_xor_sync(full, a.w, o);
    }
    __shared__ float4 sm4[8];
    int wid = t >> 5, lane = t & 31;
    if (lane == 0) sm4[wid] = a;
    __syncthreads();
    if (t == 0){
        float4 s = make_float4(0,0,0,0);
        #pragma unroll
        for (int w2 = 0; w2 < 8; w2++){
            float4 v = sm4[w2];
            s.x+=v.x; s.y+=v.y; s.z+=v.z; s.w+=v.w;
        }
        const float inv = 1.0f/8192.0f;
        g_glob[0*256+b] = s.x*inv;
        g_glob[1*256+b] = s.y*inv;
        g_glob[2*256+b] = s.z*inv;
        g_glob[3*256+b] = s.w*inv;
    }
}

// ============================================================
// GEMM phase: Out = relu(X[256,K] @ W[K,256] + bias [+G])
// X k-major. 256 blocks x 256 threads; tile 8 rows x 32 cols.
// ============================================================
#define XD_ULL 1024
#define WF_F   4096

__device__ __forceinline__ void prime_W(const float* __restrict__ Wg, float* Wf,
                                        int c0, int t){
    #pragma unroll
    for (int u = 0; u < 4; u++){
        int idx4 = t + u*256;
        int wk = idx4 >> 3, ws = idx4 & 7;
        cp_async16(Wf + wk*32 + ws*4, Wg + (size_t)wk*256 + c0 + ws*4);
    }
    cp_commit();
}

template<int NCH, bool WRITE_T>
__device__ __forceinline__ void gemm_phase(
    const float* __restrict__ XT, const float* __restrict__ Wg,
    const float* __restrict__ bias, const float* Gadd,
    float* __restrict__ Out, ull* Xd, float* Wf)
{
    int t  = threadIdx.x;
    int c0 = ((int)blockIdx.x & 7) * 32;
    int r0 = ((int)blockIdx.x >> 3) * 8;
    int rp = t & 3, qc = (t >> 2) & 7, ks = t >> 5;
    int kk = t >> 1, seg = t & 1;

    {
        float4 xv = *(const float4*)(XT + (size_t)kk*256 + r0 + seg*4);
        ull* dst = Xd + kk*8 + seg*4;
        ulonglong2 d0, d1;
        d0.x = pack2_(xv.x, xv.x); d0.y = pack2_(xv.y, xv.y);
        d1.x = pack2_(xv.z, xv.z); d1.y = pack2_(xv.w, xv.w);
        *(ulonglong2*)dst = d0;
        *(ulonglong2*)(dst+2) = d1;
    }

    ull aA0=0ULL, aA1=0ULL, aB0=0ULL, aB1=0ULL;
    float4 xn;

    #pragma unroll 1
    for (int ch = 0; ch < NCH; ch++){
        ull*   Xc = Xd + (ch & 1)*XD_ULL;
        float* Wc = Wf + (ch & 1)*WF_F;
        if (ch + 1 < NCH){
            float* Wn2 = Wf + ((ch+1)&1)*WF_F;
            #pragma unroll
            for (int u = 0; u < 4; u++){
                int idx4 = t + u*256;
                int wk = idx4 >> 3, ws = idx4 & 7;
                cp_async16(Wn2 + wk*32 + ws*4,
                           Wg + (size_t)((ch+1)*128 + wk)*256 + c0 + ws*4);
            }
            cp_commit();
            xn = *(const float4*)(XT + (size_t)((ch+1)*128 + kk)*256 + r0 + seg*4);
            cp_wait1();
        } else {
            cp_wait0();
        }
        __syncthreads();

        const ull*   xb = Xc + (ks*16)*8 + 2*rp;
        const float* wb = Wc + (ks*16)*32 + qc*4;
        #pragma unroll 4
        for (int k2 = 0; k2 < 16; k2++){
            ulonglong2 xd = *(const ulonglong2*)(xb + k2*8);
            ulonglong2 wv = *(const ulonglong2*)(wb + k2*32);
            aA0 = fma2_(wv.x, xd.x, aA0);
            aA1 = fma2_(wv.y, xd.x, aA1);
            aB0 = fma2_(wv.x, xd.y, aB0);
            aB1 = fma2_(wv.y, xd.y, aB1);
        }
        __syncthreads();

        if (ch + 1 < NCH){
            ull* dst = Xd + ((ch+1)&1)*XD_ULL + kk*8 + seg*4;
            ulonglong2 d0, d1;
            d0.x = pack2_(xn.x, xn.x); d0.y = pack2_(xn.y, xn.y);
            d1.x = pack2_(xn.z, xn.z); d1.y = pack2_(xn.w, xn.w);
            *(ulonglong2*)dst = d0;
            *(ulonglong2*)(dst+2) = d1;
        }
    }

    ull* PART = Xd;
    {
        ull* dst = PART + (size_t)t*4;
        ulonglong2 p0, p1;
        p0.x = aA0; p0.y = aA1;
        p1.x = aB0; p1.y = aB1;
        *(ulonglong2*)dst = p0;
        *(ulonglong2*)(dst+2) = p1;
    }
    __syncthreads();

    if (t < 32){
        int prp = t & 3, pqc = (t >> 2) & 7;
        float2 e01 = make_float2(0.f,0.f), e23 = e01, o01 = e01, o23 = e01;
        #pragma unroll
        for (int s = 0; s < 8; s++){
            const ull* e = PART + (size_t)(s*32 + t)*4;
            ulonglong2 u0 = *(const ulonglong2*)e;
            ulonglong2 u1 = *(const ulonglong2*)(e+2);
            float2 f;
            f = unpack2_(u0.x); e01.x += f.x; e01.y += f.y;
            f = unpack2_(u0.y); e23.x += f.x; e23.y += f.y;
            f = unpack2_(u1.x); o01.x += f.x; o01.y += f.y;
            f = unpack2_(u1.y); o23.x += f.x; o23.y += f.y;
        }
        float4 bb = *(const float4*)(bias + c0 + pqc*4);
        if (Gadd){
            bb.x += Gadd[pqc*4+0]; bb.y += Gadd[pqc*4+1];
            bb.z += Gadd[pqc*4+2]; bb.w += Gadd[pqc*4+3];
        }
        float ve0 = fmaxf(e01.x + bb.x, 0.f), ve1 = fmaxf(e01.y + bb.y, 0.f);
        float ve2 = fmaxf(e23.x + bb.z, 0.f), ve3 = fmaxf(e23.y + bb.w, 0.f);
        float vo0 = fmaxf(o01.x + bb.x, 0.f), vo1 = fmaxf(o01.y + bb.y, 0.f);
        float vo2 = fmaxf(o23.x + bb.z, 0.f), vo3 = fmaxf(o23.y + bb.w, 0.f);
        int re = r0 + 2*prp, cA = c0 + pqc*4;
        if (WRITE_T){
            *(float2*)(Out + (size_t)(cA+0)*256 + re) = make_float2(ve0, vo0);
            *(float2*)(Out + (size_t)(cA+1)*256 + re) = make_float2(ve1, vo1);
            *(float2*)(Out + (size_t)(cA+2)*256 + re) = make_float2(ve2, vo2);
            *(float2*)(Out + (size_t)(cA+3)*256 + re) = make_float2(ve3, vo3);
        } else {
            *(float4*)(Out + (size_t)re*256 + cA)     = make_float4(ve0, ve1, ve2, ve3);
            *(float4*)(Out + (size_t)(re+1)*256 + cA) = make_float4(vo0, vo1, vo2, vo3);
        }
    }
    __syncthreads();
}

// ============================================================
// Kernel 2: fill | G | GEMM1 | gbar | GEMM2 | gbar | heads | sample_ln
// ============================================================
#define FUSED_SMEM_BYTES 49152

__global__ void __launch_bounds__(256, 2)
mlp_tail_kernel(const float* __restrict__ feats,
             const float* __restrict__ W1, const float* __restrict__ b1,
             const float* __restrict__ W2, const float* __restrict__ b2,
             const float* __restrict__ Wn, const float* __restrict__ bn,
             const float* __restrict__ Woff, const float* __restrict__ boff,
             const float* __restrict__ Ww, const float* __restrict__ bw,
             const float* __restrict__ gamma, const float* __restrict__ beta,
             float* __restrict__ out, int write_next)
{
    extern __shared__ ull smu[];
    ull*   Xd = smu;
    float* Wf = (float*)(smu + 2*XD_ULL);

    __shared__ float  Hs[256];
    __shared__ float  HWn[768], HWo[192], HWw[128];
    __shared__ float  HD[28];
    __shared__ float  SPx[4], SPy[4], SPz[4], SPw[4];
    __shared__ int    cq[40];
    __shared__ float  cw[40];
    __shared__ int    s_nq;
    __shared__ float2 sred[8];
    __shared__ float  s_mu, s_rstd;
    __shared__ float  Gpart[256], Gs[32], glS[256];

    int t = threadIdx.x;
    int b = blockIdx.x;
    int g = b >> 3;
    int c0 = (b & 7) * 32;
    int l_blk = b >> 6;

    prime_W(W1, Wf, c0, t);

    // ---- beta fill (skips sampled positions), overlaps GEMM pipeline
    {
        float4* out4 = (float4*)out;
        const unsigned tm = 0x5Au;
        const unsigned hm = (1u<<4)|(1u<<12)|(1u<<19)|(1u<<27);
        #pragma unroll
        for (int u = 0; u < 8; u++){
            int f = b*2048 + u*256 + t;
            int c = f >> 13;
            int p = f & 8191;
            int t3 = p >> 10, h3 = (p >> 5) & 31, w3 = p & 31;
            bool samp = ((tm >> t3) & 1u) && ((hm >> h3) & 1u) && ((hm >> w3) & 1u);
            if (!samp){
                float bb = __ldg(&beta[c]);
                out4[f] = make_float4(bb, bb, bb, bb);
            }
        }
    }

    // ---- G[j] = sum_c glob[l_blk][c] * W1[512+c][c0+j]
    glS[t] = g_glob[l_blk*256 + t];
    __syncthreads();
    {
        int j = t & 31, cs = t >> 5;
        const float* wp = W1 + (size_t)(512 + cs*32)*256 + c0 + j;
        float s0 = 0.f, s1 = 0.f;
        #pragma unroll
        for (int ci = 0; ci < 32; ci += 2){
            s0 = fmaf(glS[cs*32+ci],   __ldg(wp + (size_t)ci*256),     s0);
            s1 = fmaf(glS[cs*32+ci+1], __ldg(wp + (size_t)(ci+1)*256), s1);
        }
        Gpart[cs*32 + j] = s0 + s1;
    }
    __syncthreads();
    if (t < 32){
        float s = 0.f;
        #pragma unroll
        for (int cs = 0; cs < 8; cs++) s += Gpart[cs*32 + t];
        Gs[t] = s;
    }
    __syncthreads();

    // ---- GEMM1 (K=512) -> g_H1T (+G fold)
    gemm_phase<4, true>(g_XT, W1, b1, Gs, g_H1T, Xd, Wf);

    prime_W(W2, Wf, c0, t);
    group_bar(0, g);

    // ---- GEMM2 (K=256) -> g_H2
    gemm_phase<2, false>(g_H1T, W2, b2, nullptr, g_H2, Xd, Wf);
    group_bar(1, g);

    // ---- heads (28 parallel 8-lane dots) + dedup, row rr = b
    int rr = b;
    int p  = flat_idx(rr & 63);

    Hs[t] = g_H2[(size_t)rr*256 + t];
    for (int k = t; k < 768; k += 256) HWn[k] = __ldg(&Wn[k]);
    if (t < 192) HWo[t] = __ldg(&Woff[t]);
    if (t < 128) HWw[t] = __ldg(&Ww[t]);
    __syncthreads();

    {
        int oid = t >> 3, sl = t & 7;
        float s = 0.f;
        if (oid < 3){
            #pragma unroll 8
            for (int i = 0; i < 32; i++){
                int k = sl + 8*i;
                s = fmaf(Hs[k], HWn[k*3 + oid], s);
            }
        } else if (oid >= 8 && oid < 20){
            int v = oid - 8;
            int no = v / 3, jo = v - no*3;
            #pragma unroll
            for (int i = 0; i < 8; i++){
                int dd = sl + 8*i;
                s = fmaf(Hs[no*64+dd], HWo[dd*3 + jo], s);
            }
        } else if (oid >= 20 && oid < 28){
            int v = oid - 20;
            int no = v >> 1, comp = v & 1;
            #pragma unroll
            for (int i = 0; i < 8; i++){
                int dd = sl + 8*i;
                s = fmaf(Hs[no*64+dd], HWw[dd*2 + comp], s);
            }
        }
        const unsigned full = 0xffffffffu;
        s += __shfl_xor_sync(full, s, 4);
        s += __shfl_xor_sync(full, s, 2);
        s += __shfl_xor_sync(full, s, 1);
        if (sl == 0 && oid < 28) HD[oid] = s;
    }
    __syncthreads();

    if (t == 0){
        int tq = p >> 10, hq = (p >> 5) & 31, wq = p & 31;
        float tn = (float)tq * (1.0f/7.0f);
        float hn = (float)hq * (1.0f/31.0f);
        float wn = (float)wq * (1.0f/31.0f);
        float ivt = invsigf_(tn), ivh = invsigf_(hn), ivw = invsigf_(wn);
        float bo0 = boff[0], bo1 = boff[1], bo2 = boff[2];
        float bw0 = bw[0],  bw1 = bw[1];

        #pragma unroll
        for (int no = 0; no < 4; no++){
            float o0 = HD[8+no*3+0] + bo0;
            float o1 = HD[8+no*3+1] + bo1;
            float o2 = HD[8+no*3+2] + bo2;
            float st = sigmoidf_(ivt + o0)*2.0f - 1.0f;
            float sh = sigmoidf_(ivh + o1)*2.0f - 1.0f;
            float sw = sigmoidf_(ivw + o2)*2.0f - 1.0f;
            SPx[no] = ((st + 1.0f)*32.0f - 1.0f)*0.5f;
            SPy[no] = ((sh + 1.0f)*32.0f - 1.0f)*0.5f;
            SPz[no] = ((sw + 1.0f)*8.0f  - 1.0f)*0.5f;
            float za = HD[20+no*2] + bw0, zb = HD[21+no*2] + bw1;
            SPw[no] = 1.0f/(1.0f + expf(za - zb));
        }

        if (write_next){
            float d0 = sigmoidf_(ivt + HD[0] + bn[0]) * 7.0f;
            float d1 = sigmoidf_(ivh + HD[1] + bn[1]) * 31.0f;
            float d2 = sigmoidf_(ivw + HD[2] + bn[2]) * 31.0f;
            int ni = 1024*(int)rintf(d0) + 32*(int)rintf(d1) + (int)rintf(d2);
            out[FEAT_OUT_ELEMS + rr] = (float)ni;
        }
    }
    __syncthreads();

    if (t < 32){
        const unsigned full = 0xffffffffu;
        int lane = t;
        int no = lane >> 3, jj = lane & 7;
        float ix = SPx[no], iy = SPy[no], iz = SPz[no];
        float wo = SPw[no];
        float x0f = floorf(ix), y0f = floorf(iy), z0f = floorf(iz);
        int dx = jj & 1, dy = (jj >> 1) & 1, dz = jj >> 2;
        int xi = (int)x0f + dx, yi = (int)y0f + dy, zi = (int)z0f + dz;
        float fx = ix - x0f, fy = iy - y0f, fz = iz - z0f;
        float w = (dx ? fx : 1.0f-fx) * (dy ? fy : 1.0f-fy) * (dz ? fz : 1.0f-fz) * wo;
        bool valid = (xi >= 0) & (xi < W_) & (yi >= 0) & (yi < H_) & (zi >= 0) & (zi < T_);
        if (!valid) w = 0.0f;
        int q = (min(max(zi,0),T_-1)*H_ + min(max(yi,0),H_-1))*W_ + min(max(xi,0),W_-1);

        unsigned mask = __match_any_sync(full, q);
        float wsum = 0.0f;
        #pragma unroll
        for (int s2 = 0; s2 < 32; s2++){
            float wv = __shfl_sync(full, w, s2);
            int   qv = __shfl_sync(full, q, s2);
            if (qv == q) wsum += wv;
        }
        int leader = __ffs(mask) - 1;
        bool is_leader = (lane == leader);
        unsigned bal = __ballot_sync(full, is_leader);
        int pos = __popc(bal & ((1u << lane) - 1u));
        if (is_leader){ cq[pos] = q; cw[pos] = wsum; }
        __syncwarp();
        if (lane == 0){
            int nq = __popc(bal);
            bool found = false;
            for (int j2 = 0; j2 < nq; j2++){
                if (cq[j2] == p){ cw[j2] += 1.0f; found = true; break; }
            }
            if (!found){ cq[nq] = p; cw[nq] = 1.0f; nq++; }
            s_nq = nq;
        }
    }
    __syncthreads();

    // ---- sample + LN, row rr
    {
        int l  = rr >> 6;
        int c  = t;
        int nq = s_nq;
        const float* fb = feats + (size_t)c*(THW_*L_) + l;
        float acc = 0.0f;
        #pragma unroll 4
        for (int j2 = 0; j2 < nq; j2++)
            acc = fmaf(cw[j2], __ldg(fb + (size_t)cq[j2]*L_), acc);
        float v = acc;

        const unsigned full = 0xffffffffu;
        float sx = v, sy = v*v;
        #pragma unroll
        for (int o = 16; o > 0; o >>= 1){
            sx += __shfl_xor_sync(full, sx, o);
            sy += __shfl_xor_sync(full, sy, o);
        }
        int lane = t & 31, wrp = t >> 5;
        if (lane == 0) sred[wrp] = make_float2(sx, sy);
        __syncthreads();
        if (t == 0){
            float mx = 0.f, my = 0.f;
            #pragma unroll
            for (int k = 0; k < 8; k++){ mx += sred[k].x; my += sred[k].y; }
            float mu  = mx * (1.0f/256.0f);
            float var = my * (1.0f/256.0f) - mu*mu;
            s_mu = mu;
            s_rstd = rsqrtf(var + 1e-5f);
        }
        __syncthreads();

        float o = (v - s_mu) * s_rstd * __ldg(&gamma[c]) + __ldg(&beta[c]);
        out[((size_t)c*THW_ + p)*L_ + l] = o;
    }
}

// ============================================================
extern "C" void kernel_launch(void* const* d_in, const int* in_sizes, int n_in,
                              void* d_out, int out_size)
{
    const float* feats = (const float*)d_in[0];
    const float* pos   = (const float*)d_in[1];
    const float* W1    = (const float*)d_in[2];
    const float* b1    = (const float*)d_in[3];
    const float* W2    = (const float*)d_in[4];
    const float* b2    = (const float*)d_in[5];
    const float* Wn    = (const float*)d_in[6];
    const float* bn    = (const float*)d_in[7];
    // d_in[8]=Wl, d_in[9]=bl dead (softmax row-sum == 1; LN scale-invariant)
    const float* Woff  = (const float*)d_in[10];
    const float* boff  = (const float*)d_in[11];
    const float* Ww    = (const float*)d_in[12];
    const float* bw    = (const float*)d_in[13];
    const float* gamma = (const float*)d_in[14];
    const float* beta  = (const float*)d_in[15];
    float* out = (float*)d_out;

    int write_next = (out_size >= FEAT_OUT_ELEMS + NROWS) ? 1 : 0;

    static int smem_set = 0;
    if (!smem_set){
        cudaFuncSetAttribute(mlp_tail_kernel, cudaFuncAttributeMaxDynamicSharedMemorySize,
                             FUSED_SMEM_BYTES);
        smem_set = 1;
    }

    scan_kernel<<<NB, 256>>>(feats, pos);
    mlp_tail_kernel<<<NB, 256, FUSED_SMEM_BYTES>>>(feats, W1, b1, W2, b2, Wn, bn,
                                                   Woff, boff, Ww, bw, gamma, beta,
                                                   out, write_next);
}